// round 13
// baseline (speedup 1.0000x reference)
#include <cuda_runtime.h>
#include <cuda_bf16.h>
#include <cstdint>

// ---------------- problem constants ------------------------------------
#define N_NODES  100000
#define F_IN     128
#define HID      64
#define N_EDGES  1600000
#define N_GRAPHS 1000
#define PER_G    100
#define TOPK     30
#define KSZ      3
#define CONV_O   32
#define CONV_T   28
#define FLAT     896
#define G_PER_BLK 4
#define M_TILES  782              // ceil(100000/128)
#define NB_SCAN  98               // ceil(100000/1024)

// smem (floats): A planes [2][128][36], B planes [2][32][136], then h[128][64]
#define A_PL 4608
#define B_PL 4352
#define GEMM_FLOATS (2*A_PL + 2*B_PL)          // 17920
#define AGG_FLOATS  (GEMM_FLOATS + 128*64)     // 26112

// ---------------- tf32 helpers ------------------------------------------
__device__ __forceinline__ void split_tf32(float v, uint32_t& t1, uint32_t& t2) {
    asm("cvt.rna.tf32.f32 %0, %1;" : "=r"(t1) : "f"(v));
    float r = v - __uint_as_float(t1);
    asm("cvt.rna.tf32.f32 %0, %1;" : "=r"(t2) : "f"(r));
}
#define MMA_TF32(d, a, b) \
    asm volatile("mma.sync.aligned.m16n8k8.row.col.f32.tf32.tf32.f32 " \
        "{%0,%1,%2,%3}, {%4,%5,%6,%7}, {%8,%9}, {%0,%1,%2,%3};" \
        : "+f"((d)[0]), "+f"((d)[1]), "+f"((d)[2]), "+f"((d)[3]) \
        : "r"((a)[0]), "r"((a)[1]), "r"((a)[2]), "r"((a)[3]), \
          "r"((b)[0]), "r"((b)[1]))

// ---------------- scratch ----------------------------------------------
__device__ int   g_deg[N_NODES];
__device__ int   g_off[N_NODES];
__device__ int   g_cur[N_NODES];
__device__ int   g_csr[N_EDGES];
__device__ int   g_flag[NB_SCAN];
__device__ int   g_agg[NB_SCAN];
__device__ int   g_incl[NB_SCAN];
__device__ float g_TSa[(size_t)N_NODES * 128];   // ping
__device__ float g_TSb[(size_t)N_NODES * 128];   // pong
__device__ float g_Bimg[65536];                  // tf32 B planes

// ---------------- init: zero deg + reset scan flags + prepB ------------
__global__ void k_init(const float* __restrict__ Wl1, const float* __restrict__ Wr1,
                       const float* __restrict__ Wl2, const float* __restrict__ Wr2,
                       const float* __restrict__ Wl3, const float* __restrict__ Wr3) {
    int i = blockIdx.x * blockDim.x + threadIdx.x;
    if (i < N_NODES) g_deg[i] = 0;
    if (i < NB_SCAN) g_flag[i] = 0;
    if (i < 32768) {
        const float *Wl, *Wr; int base, K, rem = i;
        if (i < 16384)      { Wl = Wl1; Wr = Wr1; base = 0;     K = 128; }
        else if (i < 24576) { Wl = Wl2; Wr = Wr2; base = 32768; K = 64;  rem = i - 16384; }
        else                { Wl = Wl3; Wr = Wr3; base = 49152; K = 64;  rem = i - 24576; }
        int k = rem >> 7, n = rem & 127;
        float v = (n < 64) ? Wl[k * 64 + n] : Wr[k * 64 + (n - 64)];
        uint32_t t1, t2;
        split_tf32(v, t1, t2);
        g_Bimg[base + k * 128 + n]           = __uint_as_float(t1);
        g_Bimg[base + K * 128 + k * 128 + n] = __uint_as_float(t2);
    }
}

__global__ void k_count(const int* __restrict__ dst) {
    int e = blockIdx.x * blockDim.x + threadIdx.x;
    if (e < N_EDGES) atomicAdd(&g_deg[dst[e]], 1);
}

// ---------------- single-kernel decoupled-lookback scan ------------------
__global__ void __launch_bounds__(1024) k_scan_lb() {
    __shared__ int s[1024];
    __shared__ int s_ex;
    int b = blockIdx.x, tid = threadIdx.x;
    int i = b * 1024 + tid;
    int v = (i < N_NODES) ? g_deg[i] : 0;
    s[tid] = v;
    __syncthreads();
    for (int d = 1; d < 1024; d <<= 1) {
        int t = (tid >= d) ? s[tid - d] : 0;
        __syncthreads();
        s[tid] += t;
        __syncthreads();
    }
    if (tid == 0) {
        int tot = s[1023];
        if (b == 0) {
            g_incl[0] = tot;
            __threadfence();
            ((volatile int*)g_flag)[0] = 2;
            s_ex = 0;
        } else {
            g_agg[b] = tot;
            __threadfence();
            ((volatile int*)g_flag)[b] = 1;
            int ex = 0, p = b - 1;
            while (true) {
                int f;
                do { f = ((volatile int*)g_flag)[p]; } while (f == 0);
                if (f == 2) { ex += ((volatile int*)g_incl)[p]; break; }
                ex += ((volatile int*)g_agg)[p];
                --p;
            }
            g_incl[b] = ex + tot;
            __threadfence();
            ((volatile int*)g_flag)[b] = 2;
            s_ex = ex;
        }
    }
    __syncthreads();
    if (i < N_NODES) {
        int o = s_ex + s[tid] - v;   // exclusive
        g_off[i] = o;
        g_cur[i] = o;
    }
}

__global__ void k_fill_csr(const int* __restrict__ src, const int* __restrict__ dst) {
    int e = blockIdx.x * blockDim.x + threadIdx.x;
    if (e < N_EDGES) {
        int pos = atomicAdd(&g_cur[dst[e]], 1);
        g_csr[pos] = src[e];
    }
}

// ---------------- 3xTF32 GEMM, optionally fused with agg-staging ---------
// AGG=false: A = Ax (N x K global).  AGG=true (K=64): A rows computed in-kernel:
//   h[r] = relu(mean_{j->r} Tp[j,:] + Sp[r,:] + bias), staged into smem.
// Output: T = C[:, :64], S = C[:, 64:].
template<int K, bool AGG>
__global__ void __launch_bounds__(256) k_gemm(
    const float* __restrict__ Ax, const float* __restrict__ Tp,
    const float* __restrict__ Sp, const float* __restrict__ bias,
    const float* __restrict__ Bg,
    float* __restrict__ T, float* __restrict__ S) {
    extern __shared__ float sm[];
    float* As = sm;                    // [2][128][36]
    float* Bs = sm + 2 * A_PL;         // [2][32][136]
    float* Hs = sm + GEMM_FLOATS;      // [128][64] (AGG only)
    const int tid = threadIdx.x, lane = tid & 31, wid = tid >> 5;
    const int m0 = blockIdx.x * 128;
    const int warp_m = (wid & 3) * 32;
    const int warp_n = (wid >> 2) * 64;
    const int gi = lane >> 2, ti = lane & 3;

    if (AGG) {
        int lane2 = lane * 2;
        float2 bv = *reinterpret_cast<const float2*>(bias + lane2);
        for (int r = wid; r < 128; r += 8) {
            int node = m0 + r;
            float2 a = make_float2(0.f, 0.f);
            if (node < N_NODES) {
                int beg = g_off[node], d = g_deg[node];
                for (int e = beg; e < beg + d; ++e) {
                    int sN = g_csr[e];
                    float2 v = *reinterpret_cast<const float2*>(Tp + (size_t)sN * 64 + lane2);
                    a.x += v.x; a.y += v.y;
                }
                float inv = 1.f / (float)(d > 0 ? d : 1);
                float2 sv = *reinterpret_cast<const float2*>(Sp + (size_t)node * 64 + lane2);
                a.x = a.x * inv + sv.x + bv.x;  a.x = a.x > 0.f ? a.x : 0.f;
                a.y = a.y * inv + sv.y + bv.y;  a.y = a.y > 0.f ? a.y : 0.f;
            }
            *reinterpret_cast<float2*>(Hs + r * 64 + lane2) = a;
        }
        __syncthreads();
    }

    float acc[2][8][4];
#pragma unroll
    for (int mt = 0; mt < 2; ++mt)
#pragma unroll
        for (int nt = 0; nt < 8; ++nt)
#pragma unroll
            for (int c = 0; c < 4; ++c) acc[mt][nt][c] = 0.f;

    for (int k0 = 0; k0 < K; k0 += 32) {
        // ---- stage A: 128 rows x 32 k -> 2 tf32 planes
#pragma unroll
        for (int it = 0; it < 4; ++it) {
            int idx = it * 256 + tid;
            int row = idx >> 3, kq = (idx & 7) << 2;
            float4 v;
            if (AGG) {
                v = *reinterpret_cast<const float4*>(Hs + row * 64 + k0 + kq);
            } else {
                int grow = m0 + row;
                v = (grow < N_NODES)
                    ? *reinterpret_cast<const float4*>(Ax + (size_t)grow * K + k0 + kq)
                    : make_float4(0.f, 0.f, 0.f, 0.f);
            }
            uint32_t h1[4], h2[4];
            split_tf32(v.x, h1[0], h2[0]);
            split_tf32(v.y, h1[1], h2[1]);
            split_tf32(v.z, h1[2], h2[2]);
            split_tf32(v.w, h1[3], h2[3]);
            float* p0 = As + row * 36 + kq;
            *reinterpret_cast<float4*>(p0) = make_float4(
                __uint_as_float(h1[0]), __uint_as_float(h1[1]),
                __uint_as_float(h1[2]), __uint_as_float(h1[3]));
            *reinterpret_cast<float4*>(p0 + A_PL) = make_float4(
                __uint_as_float(h2[0]), __uint_as_float(h2[1]),
                __uint_as_float(h2[2]), __uint_as_float(h2[3]));
        }
        // ---- stage B: 2 planes x 32 k x 128 n
#pragma unroll
        for (int it = 0; it < 8; ++it) {
            int idx = it * 256 + tid;
            int pl = idx >> 10, rem = idx & 1023;
            int kk = rem >> 5, nq = (rem & 31) << 2;
            float4 v = *reinterpret_cast<const float4*>(
                Bg + (size_t)pl * (K * 128) + (size_t)(k0 + kk) * 128 + nq);
            *reinterpret_cast<float4*>(Bs + pl * B_PL + kk * 136 + nq) = v;
        }
        __syncthreads();

#pragma unroll
        for (int ks = 0; ks < 4; ++ks) {
            uint32_t af[2][2][4];
#pragma unroll
            for (int mt = 0; mt < 2; ++mt)
#pragma unroll
                for (int pl = 0; pl < 2; ++pl) {
                    const float* b = As + pl * A_PL + (warp_m + mt * 16 + gi) * 36 + ks * 8 + ti;
                    af[mt][pl][0] = __float_as_uint(b[0]);
                    af[mt][pl][1] = __float_as_uint(b[8 * 36]);
                    af[mt][pl][2] = __float_as_uint(b[4]);
                    af[mt][pl][3] = __float_as_uint(b[8 * 36 + 4]);
                }
            uint32_t bf[8][2][2];
#pragma unroll
            for (int nt = 0; nt < 8; ++nt)
#pragma unroll
                for (int pl = 0; pl < 2; ++pl) {
                    const float* b = Bs + pl * B_PL + (ks * 8 + ti) * 136 + warp_n + nt * 8 + gi;
                    bf[nt][pl][0] = __float_as_uint(b[0]);
                    bf[nt][pl][1] = __float_as_uint(b[4 * 136]);
                }
#pragma unroll
            for (int mt = 0; mt < 2; ++mt)
#pragma unroll
                for (int nt = 0; nt < 8; ++nt) {
                    MMA_TF32(acc[mt][nt], af[mt][1], bf[nt][0]);   // A2*B1
                    MMA_TF32(acc[mt][nt], af[mt][0], bf[nt][1]);   // A1*B2
                    MMA_TF32(acc[mt][nt], af[mt][0], bf[nt][0]);   // A1*B1
                }
        }
        __syncthreads();
    }

    float* O = warp_n ? S : T;
#pragma unroll
    for (int mt = 0; mt < 2; ++mt) {
        int row0 = m0 + warp_m + mt * 16 + gi;
#pragma unroll
        for (int nt = 0; nt < 8; ++nt) {
            int col = nt * 8 + 2 * ti;
            if (row0 < N_NODES)
                *reinterpret_cast<float2*>(O + (size_t)row0 * 64 + col) =
                    make_float2(acc[mt][nt][0], acc[mt][nt][1]);
            if (row0 + 8 < N_NODES)
                *reinterpret_cast<float2*>(O + (size_t)(row0 + 8) * 64 + col) =
                    make_float2(acc[mt][nt][2], acc[mt][nt][3]);
        }
    }
}

// ---------------- tail: agg(keys) + sort + selective agg + conv + MLP ----
// One block = 4 graphs (400 nodes). Keys need only channel 63 (4B gathers);
// full 64-wide gather only for the 120 selected nodes.
__global__ void __launch_bounds__(256) k_tail(
    const float* __restrict__ Tp, const float* __restrict__ Sp,
    const float* __restrict__ b3,
    const float* __restrict__ cw, const float* __restrict__ cb,
    const float* __restrict__ w1, const float* __restrict__ bb1,
    const float* __restrict__ w2, const float* __restrict__ bb2,
    float* __restrict__ out) {
    extern __shared__ float sm[];
    float* cws  = sm;                    // 6144
    float* tk   = cws + 6144;            // 4*1920
    float* yf   = tk + 7680;             // 4*896
    float* keys = yf + 3584;             // 400
    float* z    = keys + 400;            // 256
    int*   sel  = (int*)(z + 256);       // 120
    const int tid = threadIdx.x, lane = tid & 31, wid = tid >> 5;
    const int base = blockIdx.x * (G_PER_BLK * PER_G);

    for (int i = tid; i < CONV_O * HID * KSZ; i += 256) cws[i] = cw[i];

    // phase 1: sort keys = h[node][63] (channel-63-only gather)
    float b63 = __ldg(b3 + 63);
    for (int n = tid; n < G_PER_BLK * PER_G; n += 256) {
        int node = base + n;
        int beg = g_off[node], d = g_deg[node];
        float acc = 0.f;
        for (int e = beg; e < beg + d; ++e)
            acc += __ldg(Tp + (size_t)g_csr[e] * 64 + 63);
        float k = acc / (float)(d > 0 ? d : 1) + __ldg(Sp + (size_t)node * 64 + 63) + b63;
        keys[n] = k > 0.f ? k : 0.f;
    }
    __syncthreads();

    // phase 2: stable descending rank per graph
    for (int n = tid; n < G_PER_BLK * PER_G; n += 256) {
        int gl = n / PER_G, i = n % PER_G;
        const float* kk = keys + gl * PER_G;
        float ki = kk[i];
        int r = 0;
#pragma unroll 4
        for (int j = 0; j < PER_G; ++j) {
            float kj = kk[j];
            r += (kj > ki) || (kj == ki && j < i);
        }
        if (r < TOPK) sel[gl * TOPK + r] = i;
    }
    __syncthreads();

    // phase 3: full 64-wide agg for the 120 selected nodes (warp per slot)
    {
        int lane2 = lane * 2;
        float2 bv = *reinterpret_cast<const float2*>(b3 + lane2);
        for (int slot = wid; slot < G_PER_BLK * TOPK; slot += 8) {
            int gl = slot / TOPK, r = slot % TOPK;
            int node = base + gl * PER_G + sel[gl * TOPK + r];
            int beg = g_off[node], d = g_deg[node];
            float2 a = make_float2(0.f, 0.f);
            for (int e = beg; e < beg + d; ++e) {
                float2 v = *reinterpret_cast<const float2*>(Tp + (size_t)g_csr[e] * 64 + lane2);
                a.x += v.x; a.y += v.y;
            }
            float inv = 1.f / (float)(d > 0 ? d : 1);
            float2 sv = *reinterpret_cast<const float2*>(Sp + (size_t)node * 64 + lane2);
            a.x = a.x * inv + sv.x + bv.x;  a.x = a.x > 0.f ? a.x : 0.f;
            a.y = a.y * inv + sv.y + bv.y;  a.y = a.y > 0.f ? a.y : 0.f;
            tk[gl * (TOPK * HID) + r * 64 + lane2]     = a.x;
            tk[gl * (TOPK * HID) + r * 64 + lane2 + 1] = a.y;
        }
    }
    __syncthreads();

    // conv1d VALID + relu
    for (int idx = tid; idx < G_PER_BLK * FLAT; idx += 256) {
        int gl = idx / FLAT, rem = idx % FLAT;
        int o = rem / CONV_T, t = rem % CONV_T;
        float acc = __ldg(cb + o);
        const float* tkg = tk + gl * (TOPK * HID);
        const float* cwo = cws + o * (HID * KSZ);
#pragma unroll 8
        for (int i = 0; i < HID; ++i) {
            const float* cwp = cwo + i * KSZ;
            acc += tkg[(t + 0) * HID + i] * cwp[0];
            acc += tkg[(t + 1) * HID + i] * cwp[1];
            acc += tkg[(t + 2) * HID + i] * cwp[2];
        }
        yf[gl * FLAT + rem] = acc > 0.f ? acc : 0.f;
    }
    __syncthreads();

    // dense 896 -> 64 + relu
    {
        int gl = tid >> 6, hh = tid & 63;
        float acc = 0.f;
        const float* yg = yf + gl * FLAT;
        for (int f = 0; f < FLAT; ++f)
            acc += yg[f] * __ldg(w1 + (size_t)f * 64 + hh);
        float v = acc + __ldg(bb1 + hh);
        z[gl * 64 + hh] = v > 0.f ? v : 0.f;
    }
    __syncthreads();

    if (tid < G_PER_BLK) {
        float s = __ldg(bb2);
#pragma unroll
        for (int h = 0; h < HID; ++h) s += z[tid * 64 + h] * __ldg(w2 + h);
        out[blockIdx.x * G_PER_BLK + tid] = s;
    }
}

// ---------------- launch ------------------------------------------------
extern "C" void kernel_launch(void* const* d_in, const int* in_sizes, int n_in,
                              void* d_out, int out_size) {
    const float* x   = (const float*)d_in[0];
    const int*   src = (const int*)d_in[1];
    const int*   dst = (const int*)d_in[2];
    const float* wl1 = (const float*)d_in[4];
    const float* wr1 = (const float*)d_in[5];
    const float* b1  = (const float*)d_in[6];   (void)b1;
    const float* wl2 = (const float*)d_in[7];
    const float* wr2 = (const float*)d_in[8];
    const float* b2  = (const float*)d_in[9];
    const float* wl3 = (const float*)d_in[10];
    const float* wr3 = (const float*)d_in[11];
    const float* b3  = (const float*)d_in[12];
    const float* cw  = (const float*)d_in[13];
    const float* cb  = (const float*)d_in[14];
    const float* w1  = (const float*)d_in[15];
    const float* bb1 = (const float*)d_in[16];
    const float* w2  = (const float*)d_in[17];
    const float* bb2 = (const float*)d_in[18];
    float* out = (float*)d_out;

    float *p_A, *p_B, *p_W;
    cudaGetSymbolAddress((void**)&p_A, g_TSa);
    cudaGetSymbolAddress((void**)&p_B, g_TSb);
    cudaGetSymbolAddress((void**)&p_W, g_Bimg);
    float *Ta = p_A, *Sa = p_A + (size_t)N_NODES * 64;
    float *Tb = p_B, *Sb = p_B + (size_t)N_NODES * 64;

    const int GEMM_SZ = GEMM_FLOATS * 4;   // 71680
    const int AGG_SZ  = AGG_FLOATS * 4;    // 104448
    const int TAIL_SZ = (6144 + 7680 + 3584 + 400 + 256) * 4 + 120 * 4;
    cudaFuncSetAttribute(k_gemm<128, false>, cudaFuncAttributeMaxDynamicSharedMemorySize, GEMM_SZ);
    cudaFuncSetAttribute(k_gemm<64, true>,   cudaFuncAttributeMaxDynamicSharedMemorySize, AGG_SZ);
    cudaFuncSetAttribute(k_tail,             cudaFuncAttributeMaxDynamicSharedMemorySize, TAIL_SZ);

    // 0: init (zero deg, reset scan flags, tf32 B images)
    k_init<<<(N_NODES + 255) / 256, 256>>>(wl1, wr1, wl2, wr2, wl3, wr3);
    // 1: degree count
    k_count<<<(N_EDGES + 255) / 256, 256>>>(dst);
    // 2: single-kernel scan (decoupled lookback; grid 98 <= SM count)
    k_scan_lb<<<NB_SCAN, 1024>>>();
    // 3: CSR bucket fill
    k_fill_csr<<<(N_EDGES + 255) / 256, 256>>>(src, dst);
    // 4: layer-1 GEMM on x (K=128) -> T1,S1 in buffer A
    k_gemm<128, false><<<M_TILES, 256, GEMM_SZ>>>(x, nullptr, nullptr, nullptr, p_W, Ta, Sa);
    // 5: layer-2 fused agg+GEMM (reads T1,S1 + b1) -> T2,S2 in buffer B
    k_gemm<64, true><<<M_TILES, 256, AGG_SZ>>>(nullptr, Ta, Sa, b1, p_W + 32768, Tb, Sb);
    // 6: layer-3 fused agg+GEMM (reads T2,S2 + b2) -> T3,S3 in buffer A
    k_gemm<64, true><<<M_TILES, 256, AGG_SZ>>>(nullptr, Tb, Sb, b2, p_W + 49152, Ta, Sa);
    // 7: tail = final agg (key-gather + selective full gather) + sort + conv + MLP
    k_tail<<<N_GRAPHS / G_PER_BLK, 256, TAIL_SZ>>>(Ta, Sa, b3, cw, cb, w1, bb1, w2, bb2, out);
}

// round 15
// speedup vs baseline: 1.2146x; 1.2146x over previous
#include <cuda_runtime.h>
#include <cuda_bf16.h>
#include <cstdint>

// ---------------- problem constants ------------------------------------
#define N_NODES  100000
#define F_IN     128
#define HID      64
#define N_EDGES  1600000
#define N_GRAPHS 1000
#define PER_G    100
#define TOPK     30
#define KSZ      3
#define CONV_O   32
#define CONV_T   28
#define FLAT     896
#define G_PER_BLK 4
#define M_TILES  782              // ceil(100000/128)
#define NB_SCAN  98               // ceil(100000/1024)

// smem (floats): A planes [2][128][36], B planes [2][32][136]
#define A_PL 4608
#define B_PL 4352
#define GEMM_FLOATS (2*A_PL + 2*B_PL)          // 17920

// ---------------- tf32 helpers ------------------------------------------
__device__ __forceinline__ void split_tf32(float v, uint32_t& t1, uint32_t& t2) {
    asm("cvt.rna.tf32.f32 %0, %1;" : "=r"(t1) : "f"(v));
    float r = v - __uint_as_float(t1);
    asm("cvt.rna.tf32.f32 %0, %1;" : "=r"(t2) : "f"(r));
}
#define MMA_TF32(d, a, b) \
    asm volatile("mma.sync.aligned.m16n8k8.row.col.f32.tf32.tf32.f32 " \
        "{%0,%1,%2,%3}, {%4,%5,%6,%7}, {%8,%9}, {%0,%1,%2,%3};" \
        : "+f"((d)[0]), "+f"((d)[1]), "+f"((d)[2]), "+f"((d)[3]) \
        : "r"((a)[0]), "r"((a)[1]), "r"((a)[2]), "r"((a)[3]), \
          "r"((b)[0]), "r"((b)[1]))

// ---------------- scratch ----------------------------------------------
__device__ int   g_deg[N_NODES];
__device__ int   g_off[N_NODES];
__device__ int   g_cur[N_NODES];
__device__ int   g_csr[N_EDGES];
__device__ int   g_flag[NB_SCAN];
__device__ int   g_aggv[NB_SCAN];
__device__ int   g_incl[NB_SCAN];
__device__ float g_TS[(size_t)N_NODES * 128];    // T | S from current GEMM
__device__ float g_h[(size_t)N_NODES * 64];      // aggregated hidden
__device__ float g_Bimg[65536];                  // tf32 B planes

// ---------------- init: zero deg + scan flags + tf32 B images ----------
__global__ void k_init(const float* __restrict__ Wl1, const float* __restrict__ Wr1,
                       const float* __restrict__ Wl2, const float* __restrict__ Wr2,
                       const float* __restrict__ Wl3, const float* __restrict__ Wr3) {
    int i = blockIdx.x * blockDim.x + threadIdx.x;
    if (i < N_NODES) g_deg[i] = 0;
    if (i < NB_SCAN) g_flag[i] = 0;
    if (i < 32768) {
        const float *Wl, *Wr; int base, K, rem = i;
        if (i < 16384)      { Wl = Wl1; Wr = Wr1; base = 0;     K = 128; }
        else if (i < 24576) { Wl = Wl2; Wr = Wr2; base = 32768; K = 64;  rem = i - 16384; }
        else                { Wl = Wl3; Wr = Wr3; base = 49152; K = 64;  rem = i - 24576; }
        int k = rem >> 7, n = rem & 127;
        float v = (n < 64) ? Wl[k * 64 + n] : Wr[k * 64 + (n - 64)];
        uint32_t t1, t2;
        split_tf32(v, t1, t2);
        g_Bimg[base + k * 128 + n]           = __uint_as_float(t1);
        g_Bimg[base + K * 128 + k * 128 + n] = __uint_as_float(t2);
    }
}

__global__ void k_count(const int* __restrict__ dst) {
    int e = blockIdx.x * blockDim.x + threadIdx.x;
    if (e < N_EDGES) atomicAdd(&g_deg[dst[e]], 1);
}

// ---------------- single-kernel decoupled-lookback scan ------------------
__global__ void __launch_bounds__(1024) k_scan_lb() {
    __shared__ int s[1024];
    __shared__ int s_ex;
    int b = blockIdx.x, tid = threadIdx.x;
    int i = b * 1024 + tid;
    int v = (i < N_NODES) ? g_deg[i] : 0;
    s[tid] = v;
    __syncthreads();
    for (int d = 1; d < 1024; d <<= 1) {
        int t = (tid >= d) ? s[tid - d] : 0;
        __syncthreads();
        s[tid] += t;
        __syncthreads();
    }
    if (tid == 0) {
        int tot = s[1023];
        if (b == 0) {
            g_incl[0] = tot;
            __threadfence();
            ((volatile int*)g_flag)[0] = 2;
            s_ex = 0;
        } else {
            g_aggv[b] = tot;
            __threadfence();
            ((volatile int*)g_flag)[b] = 1;
            int ex = 0, p = b - 1;
            while (true) {
                int f;
                do { f = ((volatile int*)g_flag)[p]; } while (f == 0);
                if (f == 2) { ex += ((volatile int*)g_incl)[p]; break; }
                ex += ((volatile int*)g_aggv)[p];
                --p;
            }
            g_incl[b] = ex + tot;
            __threadfence();
            ((volatile int*)g_flag)[b] = 2;
            s_ex = ex;
        }
    }
    __syncthreads();
    if (i < N_NODES) {
        int o = s_ex + s[tid] - v;   // exclusive
        g_off[i] = o;
        g_cur[i] = o;
    }
}

__global__ void k_fill_csr(const int* __restrict__ src, const int* __restrict__ dst) {
    int e = blockIdx.x * blockDim.x + threadIdx.x;
    if (e < N_EDGES) {
        int pos = atomicAdd(&g_cur[dst[e]], 1);
        g_csr[pos] = src[e];
    }
}

// ---------------- 3xTF32 mma.sync GEMM (standalone, high-occupancy agg kept separate)
template<int K>
__global__ void __launch_bounds__(256) k_mma_gemm(
    const float* __restrict__ A, const float* __restrict__ Bg,
    float* __restrict__ T, float* __restrict__ S) {
    extern __shared__ float sm[];
    float* As = sm;                    // [2][128][36]
    float* Bs = sm + 2 * A_PL;         // [2][32][136]
    const int tid = threadIdx.x, lane = tid & 31, wid = tid >> 5;
    const int m0 = blockIdx.x * 128;
    const int warp_m = (wid & 3) * 32;
    const int warp_n = (wid >> 2) * 64;
    const int gi = lane >> 2, ti = lane & 3;

    float acc[2][8][4];
#pragma unroll
    for (int mt = 0; mt < 2; ++mt)
#pragma unroll
        for (int nt = 0; nt < 8; ++nt)
#pragma unroll
            for (int c = 0; c < 4; ++c) acc[mt][nt][c] = 0.f;

    for (int k0 = 0; k0 < K; k0 += 32) {
#pragma unroll
        for (int it = 0; it < 4; ++it) {
            int idx = it * 256 + tid;
            int row = idx >> 3, kq = (idx & 7) << 2;
            int grow = m0 + row;
            float4 v = (grow < N_NODES)
                ? *reinterpret_cast<const float4*>(A + (size_t)grow * K + k0 + kq)
                : make_float4(0.f, 0.f, 0.f, 0.f);
            uint32_t h1[4], h2[4];
            split_tf32(v.x, h1[0], h2[0]);
            split_tf32(v.y, h1[1], h2[1]);
            split_tf32(v.z, h1[2], h2[2]);
            split_tf32(v.w, h1[3], h2[3]);
            float* p0 = As + row * 36 + kq;
            *reinterpret_cast<float4*>(p0) = make_float4(
                __uint_as_float(h1[0]), __uint_as_float(h1[1]),
                __uint_as_float(h1[2]), __uint_as_float(h1[3]));
            *reinterpret_cast<float4*>(p0 + A_PL) = make_float4(
                __uint_as_float(h2[0]), __uint_as_float(h2[1]),
                __uint_as_float(h2[2]), __uint_as_float(h2[3]));
        }
#pragma unroll
        for (int it = 0; it < 8; ++it) {
            int idx = it * 256 + tid;
            int pl = idx >> 10, rem = idx & 1023;
            int kk = rem >> 5, nq = (rem & 31) << 2;
            float4 v = *reinterpret_cast<const float4*>(
                Bg + (size_t)pl * (K * 128) + (size_t)(k0 + kk) * 128 + nq);
            *reinterpret_cast<float4*>(Bs + pl * B_PL + kk * 136 + nq) = v;
        }
        __syncthreads();

#pragma unroll
        for (int ks = 0; ks < 4; ++ks) {
            uint32_t af[2][2][4];
#pragma unroll
            for (int mt = 0; mt < 2; ++mt)
#pragma unroll
                for (int pl = 0; pl < 2; ++pl) {
                    const float* b = As + pl * A_PL + (warp_m + mt * 16 + gi) * 36 + ks * 8 + ti;
                    af[mt][pl][0] = __float_as_uint(b[0]);
                    af[mt][pl][1] = __float_as_uint(b[8 * 36]);
                    af[mt][pl][2] = __float_as_uint(b[4]);
                    af[mt][pl][3] = __float_as_uint(b[8 * 36 + 4]);
                }
            uint32_t bf[8][2][2];
#pragma unroll
            for (int nt = 0; nt < 8; ++nt)
#pragma unroll
                for (int pl = 0; pl < 2; ++pl) {
                    const float* b = Bs + pl * B_PL + (ks * 8 + ti) * 136 + warp_n + nt * 8 + gi;
                    bf[nt][pl][0] = __float_as_uint(b[0]);
                    bf[nt][pl][1] = __float_as_uint(b[4 * 136]);
                }
#pragma unroll
            for (int mt = 0; mt < 2; ++mt)
#pragma unroll
                for (int nt = 0; nt < 8; ++nt) {
                    MMA_TF32(acc[mt][nt], af[mt][1], bf[nt][0]);   // A2*B1
                    MMA_TF32(acc[mt][nt], af[mt][0], bf[nt][1]);   // A1*B2
                    MMA_TF32(acc[mt][nt], af[mt][0], bf[nt][0]);   // A1*B1
                }
        }
        __syncthreads();
    }

    float* O = warp_n ? S : T;
#pragma unroll
    for (int mt = 0; mt < 2; ++mt) {
        int row0 = m0 + warp_m + mt * 16 + gi;
#pragma unroll
        for (int nt = 0; nt < 8; ++nt) {
            int col = nt * 8 + 2 * ti;
            if (row0 < N_NODES)
                *reinterpret_cast<float2*>(O + (size_t)row0 * 64 + col) =
                    make_float2(acc[mt][nt][0], acc[mt][nt][1]);
            if (row0 + 8 < N_NODES)
                *reinterpret_cast<float2*>(O + (size_t)(row0 + 8) * 64 + col) =
                    make_float2(acc[mt][nt][2], acc[mt][nt][3]);
        }
    }
}

// ---------------- fused aggregate + epilogue (high occupancy, x4 unroll)
__global__ void __launch_bounds__(256) k_aggfuse(
    const float* __restrict__ T, const float* __restrict__ S,
    const float* __restrict__ bias, float* __restrict__ out) {
    int node = (blockIdx.x * blockDim.x + threadIdx.x) >> 5;
    int lane = threadIdx.x & 31;
    if (node >= N_NODES) return;
    int beg = g_off[node];
    int end = beg + g_deg[node];
    float2 acc = make_float2(0.f, 0.f);
    int e = beg;
    for (; e + 4 <= end; e += 4) {
        int s0 = g_csr[e], s1 = g_csr[e + 1], s2 = g_csr[e + 2], s3 = g_csr[e + 3];
        float2 v0 = *reinterpret_cast<const float2*>(T + (size_t)s0 * 64 + 2 * lane);
        float2 v1 = *reinterpret_cast<const float2*>(T + (size_t)s1 * 64 + 2 * lane);
        float2 v2 = *reinterpret_cast<const float2*>(T + (size_t)s2 * 64 + 2 * lane);
        float2 v3 = *reinterpret_cast<const float2*>(T + (size_t)s3 * 64 + 2 * lane);
        acc.x += v0.x; acc.y += v0.y;
        acc.x += v1.x; acc.y += v1.y;
        acc.x += v2.x; acc.y += v2.y;
        acc.x += v3.x; acc.y += v3.y;
    }
    for (; e < end; ++e) {
        float2 v = *reinterpret_cast<const float2*>(T + (size_t)g_csr[e] * 64 + 2 * lane);
        acc.x += v.x; acc.y += v.y;
    }
    int d = end - beg;
    float inv = 1.f / (float)(d > 0 ? d : 1);
    float2 sv = *reinterpret_cast<const float2*>(S + (size_t)node * 64 + 2 * lane);
    float2 bv = *reinterpret_cast<const float2*>(bias + 2 * lane);
    float2 r;
    r.x = acc.x * inv + sv.x + bv.x;  r.x = r.x > 0.f ? r.x : 0.f;
    r.y = acc.y * inv + sv.y + bv.y;  r.y = r.y > 0.f ? r.y : 0.f;
    *reinterpret_cast<float2*>(out + (size_t)node * 64 + 2 * lane) = r;
}

// ---------------- tail: key agg + stable sort + selective agg + conv + MLP
__global__ void __launch_bounds__(256) k_tail(
    const float* __restrict__ Tp, const float* __restrict__ Sp,
    const float* __restrict__ b3,
    const float* __restrict__ cw, const float* __restrict__ cb,
    const float* __restrict__ w1, const float* __restrict__ bb1,
    const float* __restrict__ w2, const float* __restrict__ bb2,
    float* __restrict__ out) {
    extern __shared__ float sm[];
    float* cws  = sm;                    // 6144
    float* tk   = cws + 6144;            // 4*1920
    float* yf   = tk + 7680;             // 4*896
    float* keys = yf + 3584;             // 400
    float* z    = keys + 400;            // 256
    int*   sel  = (int*)(z + 256);       // 120
    const int tid = threadIdx.x, lane = tid & 31, wid = tid >> 5;
    const int base = blockIdx.x * (G_PER_BLK * PER_G);

    for (int i = tid; i < CONV_O * HID * KSZ; i += 256) cws[i] = cw[i];

    // phase 1: sort keys = h[node][63] only (4B sector gathers)
    float b63 = __ldg(b3 + 63);
    for (int n = tid; n < G_PER_BLK * PER_G; n += 256) {
        int node = base + n;
        int beg = g_off[node], d = g_deg[node];
        float acc = 0.f;
        for (int e = beg; e < beg + d; ++e)
            acc += __ldg(Tp + (size_t)g_csr[e] * 64 + 63);
        float k = acc / (float)(d > 0 ? d : 1) + __ldg(Sp + (size_t)node * 64 + 63) + b63;
        keys[n] = k > 0.f ? k : 0.f;
    }
    __syncthreads();

    // phase 2: stable descending rank per graph
    for (int n = tid; n < G_PER_BLK * PER_G; n += 256) {
        int gl = n / PER_G, i = n % PER_G;
        const float* kk = keys + gl * PER_G;
        float ki = kk[i];
        int r = 0;
#pragma unroll 4
        for (int j = 0; j < PER_G; ++j) {
            float kj = kk[j];
            r += (kj > ki) || (kj == ki && j < i);
        }
        if (r < TOPK) sel[gl * TOPK + r] = i;
    }
    __syncthreads();

    // phase 3: full 64-wide agg for the 120 selected nodes (warp per slot)
    {
        int lane2 = lane * 2;
        float2 bv = *reinterpret_cast<const float2*>(b3 + lane2);
        for (int slot = wid; slot < G_PER_BLK * TOPK; slot += 8) {
            int gl = slot / TOPK, r = slot % TOPK;
            int node = base + gl * PER_G + sel[gl * TOPK + r];
            int beg = g_off[node], d = g_deg[node];
            float2 a = make_float2(0.f, 0.f);
            for (int e = beg; e < beg + d; ++e) {
                float2 v = *reinterpret_cast<const float2*>(Tp + (size_t)g_csr[e] * 64 + lane2);
                a.x += v.x; a.y += v.y;
            }
            float inv = 1.f / (float)(d > 0 ? d : 1);
            float2 sv = *reinterpret_cast<const float2*>(Sp + (size_t)node * 64 + lane2);
            a.x = a.x * inv + sv.x + bv.x;  a.x = a.x > 0.f ? a.x : 0.f;
            a.y = a.y * inv + sv.y + bv.y;  a.y = a.y > 0.f ? a.y : 0.f;
            tk[gl * (TOPK * HID) + r * 64 + lane2]     = a.x;
            tk[gl * (TOPK * HID) + r * 64 + lane2 + 1] = a.y;
        }
    }
    __syncthreads();

    // conv1d VALID + relu
    for (int idx = tid; idx < G_PER_BLK * FLAT; idx += 256) {
        int gl = idx / FLAT, rem = idx % FLAT;
        int o = rem / CONV_T, t = rem % CONV_T;
        float acc = __ldg(cb + o);
        const float* tkg = tk + gl * (TOPK * HID);
        const float* cwo = cws + o * (HID * KSZ);
#pragma unroll 8
        for (int i = 0; i < HID; ++i) {
            const float* cwp = cwo + i * KSZ;
            acc += tkg[(t + 0) * HID + i] * cwp[0];
            acc += tkg[(t + 1) * HID + i] * cwp[1];
            acc += tkg[(t + 2) * HID + i] * cwp[2];
        }
        yf[gl * FLAT + rem] = acc > 0.f ? acc : 0.f;
    }
    __syncthreads();

    // dense 896 -> 64 + relu
    {
        int gl = tid >> 6, hh = tid & 63;
        float acc = 0.f;
        const float* yg = yf + gl * FLAT;
        for (int f = 0; f < FLAT; ++f)
            acc += yg[f] * __ldg(w1 + (size_t)f * 64 + hh);
        float v = acc + __ldg(bb1 + hh);
        z[gl * 64 + hh] = v > 0.f ? v : 0.f;
    }
    __syncthreads();

    if (tid < G_PER_BLK) {
        float s = __ldg(bb2);
#pragma unroll
        for (int h = 0; h < HID; ++h) s += z[tid * 64 + h] * __ldg(w2 + h);
        out[blockIdx.x * G_PER_BLK + tid] = s;
    }
}

// ---------------- launch ------------------------------------------------
extern "C" void kernel_launch(void* const* d_in, const int* in_sizes, int n_in,
                              void* d_out, int out_size) {
    const float* x   = (const float*)d_in[0];
    const int*   src = (const int*)d_in[1];
    const int*   dst = (const int*)d_in[2];
    const float* wl1 = (const float*)d_in[4];
    const float* wr1 = (const float*)d_in[5];
    const float* b1  = (const float*)d_in[6];
    const float* wl2 = (const float*)d_in[7];
    const float* wr2 = (const float*)d_in[8];
    const float* b2  = (const float*)d_in[9];
    const float* wl3 = (const float*)d_in[10];
    const float* wr3 = (const float*)d_in[11];
    const float* b3  = (const float*)d_in[12];
    const float* cw  = (const float*)d_in[13];
    const float* cb  = (const float*)d_in[14];
    const float* w1  = (const float*)d_in[15];
    const float* bb1 = (const float*)d_in[16];
    const float* w2  = (const float*)d_in[17];
    const float* bb2 = (const float*)d_in[18];
    float* out = (float*)d_out;

    float *p_TS, *p_h, *p_W;
    cudaGetSymbolAddress((void**)&p_TS, g_TS);
    cudaGetSymbolAddress((void**)&p_h,  g_h);
    cudaGetSymbolAddress((void**)&p_W,  g_Bimg);
    float* p_T = p_TS;
    float* p_S = p_TS + (size_t)N_NODES * 64;

    const int GEMM_SZ = GEMM_FLOATS * 4;   // 71680
    const int TAIL_SZ = (6144 + 7680 + 3584 + 400 + 256) * 4 + 120 * 4;
    cudaFuncSetAttribute(k_mma_gemm<128>, cudaFuncAttributeMaxDynamicSharedMemorySize, GEMM_SZ);
    cudaFuncSetAttribute(k_mma_gemm<64>,  cudaFuncAttributeMaxDynamicSharedMemorySize, GEMM_SZ);
    cudaFuncSetAttribute(k_tail,          cudaFuncAttributeMaxDynamicSharedMemorySize, TAIL_SZ);

    const int aggBlocks = (N_NODES * 32 + 255) / 256;

    // 0: init  1: count  2: scan  3: fill
    k_init<<<(N_NODES + 255) / 256, 256>>>(wl1, wr1, wl2, wr2, wl3, wr3);
    k_count<<<(N_EDGES + 255) / 256, 256>>>(dst);
    k_scan_lb<<<NB_SCAN, 1024>>>();
    k_fill_csr<<<(N_EDGES + 255) / 256, 256>>>(src, dst);
    // 4: layer-1 GEMM (K=128) -> T,S      5: agg -> h    (launch #5 profiled)
    k_mma_gemm<128><<<M_TILES, 256, GEMM_SZ>>>(x, p_W, p_T, p_S);
    k_aggfuse<<<aggBlocks, 256>>>(p_T, p_S, b1, p_h);
    // 6: layer-2 GEMM (K=64)              7: agg -> h
    k_mma_gemm<64><<<M_TILES, 256, GEMM_SZ>>>(p_h, p_W + 32768, p_T, p_S);
    k_aggfuse<<<aggBlocks, 256>>>(p_T, p_S, b2, p_h);
    // 8: layer-3 GEMM (K=64) -> T,S
    k_mma_gemm<64><<<M_TILES, 256, GEMM_SZ>>>(p_h, p_W + 49152, p_T, p_S);
    // 9: tail = key agg + sort + selective full agg + conv + MLP
    k_tail<<<N_GRAPHS / G_PER_BLK, 256, TAIL_SZ>>>(p_T, p_S, b3, cw, cb, w1, bb1, w2, bb2, out);
}